// round 9
// baseline (speedup 1.0000x reference)
#include <cuda_runtime.h>
#include <math.h>

#define H 1024
#define L 4096
#define V 29
#define NB 148
#define NT 1024
#define DEPTH 5
#define SLOT_FLOATS 8192                       // 32 KB per stage
#define SMEM_FLOATS (2 * H + DEPTH * SLOT_FLOATS)
#define SMEM_BYTES (SMEM_FLOATS * 4)           // 168 KB dynamic

// ---------------- scratch (device globals) ----------------------------------
__device__ float g_scores[L];
__device__ float g_hh[4 * H];
__device__ float g_attn[H];
__device__ float g_x[H];
__device__ float g_gates[4 * H];
__device__ unsigned g_cnt = 0;
__device__ volatile unsigned g_flag = 0;

// ---------------- helpers ----------------------------------------------------
__device__ __forceinline__ float warp_sum(float v) {
#pragma unroll
    for (int o = 16; o; o >>= 1) v += __shfl_xor_sync(0xffffffffu, v, o);
    return v;
}
__device__ __forceinline__ float warp_max(float v) {
#pragma unroll
    for (int o = 16; o; o >>= 1) v = fmaxf(v, __shfl_xor_sync(0xffffffffu, v, o));
    return v;
}
__device__ __forceinline__ float sigmoidf_(float x) { return 1.0f / (1.0f + expf(-x)); }
__device__ __forceinline__ float dot4(float4 a, float4 b) {
    return a.x * b.x + a.y * b.y + a.z * b.z + a.w * b.w;
}

__device__ __forceinline__ void grid_barrier(unsigned sense) {
    __syncthreads();
    if (threadIdx.x == 0) {
        __threadfence();
        unsigned old = atomicAdd(&g_cnt, 1u);
        if (old == NB - 1) {
            g_cnt = 0;
            __threadfence();
            g_flag = sense;
        } else {
            while (g_flag != sense) { __nanosleep(32); }
        }
        __threadfence();
    }
    __syncthreads();
}

// ---------------- TMA bulk + mbarrier plumbing --------------------------------
__device__ __forceinline__ unsigned smem_u32(const void* p) {
    return (unsigned)__cvta_generic_to_shared(p);
}
__device__ __forceinline__ void mbar_init(unsigned bar) {
    asm volatile("mbarrier.init.shared.b64 [%0], %1;" :: "r"(bar), "r"(1) : "memory");
}
// elected thread: arrive + expect tx bytes, then 1D bulk copy global->smem
__device__ __forceinline__ void tma_issue(unsigned dst, const float* src,
                                          unsigned bytes, unsigned bar) {
    asm volatile("mbarrier.arrive.expect_tx.shared.b64 _, [%0], %1;"
                 :: "r"(bar), "r"(bytes) : "memory");
    asm volatile("cp.async.bulk.shared::cluster.global.mbarrier::complete_tx::bytes "
                 "[%0], [%1], %2, [%3];"
                 :: "r"(dst), "l"(src), "r"(bytes), "r"(bar) : "memory");
}
__device__ __forceinline__ void mbar_wait(unsigned bar, unsigned parity) {
    unsigned done = 0;
    while (!done) {
        asm volatile(
            "{\n\t.reg .pred p;\n\t"
            "mbarrier.try_wait.parity.acquire.cta.shared::cta.b64 p, [%1], %2, 10000000;\n\t"
            "selp.b32 %0, 1, 0, p;\n\t}"
            : "=r"(done) : "r"(bar), "r"(parity) : "memory");
    }
}

// ---------------- dot-tile mapping: phase A -----------------------------------
// tiles 0..1023: attn_W (4 rows x 2048); tiles 1024..1535: W_hh (8 rows x 1024)
__device__ __forceinline__ const float* tileA(int tile, const float* attn_W,
                                              const float* W_hh, int& RL,
                                              int& row0, int& mat, int& vecoff) {
    if (tile < 1024) { RL = 2048; mat = 0; row0 = tile * 4; vecoff = 0;
                       return attn_W + (size_t)tile * SLOT_FLOATS; }
    int u = tile - 1024;
    RL = 1024; mat = 1; row0 = u * 8; vecoff = 1024;
    return W_hh + (size_t)u * SLOT_FLOATS;
}

// consume one 32KB dot stage; mat: 0=scores 1=hh 2=comb 3=ih
__device__ __forceinline__ void consume_dot(const float4* slot, const float4* vec,
                                            int RL, int row0, int mat,
                                            const float* attn_b, const float* comb_b,
                                            const float* b_ih, const float* b_hh,
                                            float* s_part) {
    int t = threadIdx.x, warp = t >> 5, lane = t & 31;
    int R = SLOT_FLOATS / RL;         // 4 or 8 rows per stage
    int wpr = 32 / R;                 // warps per row: 8 or 4
    int row = warp / wpr, part = warp - row * wpr;
    int fo = (row * RL + part * 256) >> 2;
    int vo = (part * 256) >> 2;
    float4 w0 = slot[fo + lane],      w1 = slot[fo + 32 + lane];
    float4 v0 = vec[vo + lane],       v1 = vec[vo + 32 + lane];
    float p = dot4(w0, v0) + dot4(w1, v1);
    p = warp_sum(p);
    if (lane == 0) s_part[warp] = p;
    __syncthreads();
    if (warp < R) {
        float v = (lane < wpr) ? s_part[warp * wpr + lane] : 0.0f;
        v = warp_sum(v);
        if (lane == 0) {
            int gr = row0 + warp;
            if      (mat == 0) g_scores[gr] = v + attn_b[gr];
            else if (mat == 1) g_hh[gr] = v;
            else if (mat == 2) g_x[gr] = fmaxf(v + comb_b[gr], 0.0f);
            else               g_gates[gr] = v + g_hh[gr] + b_ih[gr] + b_hh[gr];
        }
    }
}

// ---------------- the whole decoder step in one kernel -----------------------
__global__ void __launch_bounds__(NT, 1)
k_decoder(const int* __restrict__ tok,
          const float* __restrict__ h0,
          const float* __restrict__ c0,
          const float* __restrict__ enc,
          const float* __restrict__ emb,
          const float* __restrict__ attn_W,
          const float* __restrict__ attn_b,
          const float* __restrict__ comb_W,
          const float* __restrict__ comb_b,
          const float* __restrict__ W_ih,
          const float* __restrict__ W_hh,
          const float* __restrict__ b_ih,
          const float* __restrict__ b_hh,
          const float* __restrict__ out_W,
          const float* __restrict__ out_b,
          float* __restrict__ out) {
    extern __shared__ float s_dyn[];
    float* s_vec = s_dyn;                      // 2048 floats
    float* ring  = s_dyn + 2 * H;              // DEPTH x 8192 floats
    __shared__ __align__(8) unsigned long long mbar[DEPTH];
    __shared__ float s_part[32];
    __shared__ float red[32];
    __shared__ float bcast;
    __shared__ float s_wts[28];
    __shared__ float z[32];

    const int t = threadIdx.x;
    const int warp = t >> 5, lane = t & 31;
    const int b = blockIdx.x;
    float* attn_out = out + V + 2 * H;         // [lp | h | c | attn_w]

    unsigned slot_addr[DEPTH], bar_addr[DEPTH];
    unsigned par[DEPTH];
#pragma unroll
    for (int i = 0; i < DEPTH; i++) {
        slot_addr[i] = smem_u32(ring + i * SLOT_FLOATS);
        bar_addr[i]  = smem_u32(&mbar[i]);
        par[i] = 0;
    }
    if (t == 0) {
#pragma unroll
        for (int i = 0; i < DEPTH; i++) mbar_init(bar_addr[i]);
    }
    __syncthreads();

    // ===== Phase A: attn scores + W_hh@h0, TMA pipelined ====================
    {
        const float* erow = emb + (size_t)tok[0] * H;
        s_vec[t] = erow[t];
        s_vec[H + t] = h0[t];
        if (b == 0) g_attn[t] = 0.0f;
        __syncthreads();

        const int tb = (b * 1536) / NB, te = ((b + 1) * 1536) / NB;
        const int n = te - tb;
        int RL, row0, mat, vecoff;
        if (t == 0) {
            for (int k = 0; k < (n < DEPTH ? n : DEPTH); k++) {
                const float* src = tileA(tb + k, attn_W, W_hh, RL, row0, mat, vecoff);
                tma_issue(slot_addr[k], src, SLOT_FLOATS * 4, bar_addr[k]);
            }
        }
        for (int k = 0; k < n; k++) {
            int s = k % DEPTH;
            mbar_wait(bar_addr[s], par[s]);
            par[s] ^= 1;
            tileA(tb + k, attn_W, W_hh, RL, row0, mat, vecoff);
            consume_dot((const float4*)(ring + s * SLOT_FLOATS),
                        (const float4*)(s_vec + vecoff), RL, row0, mat,
                        attn_b, comb_b, b_ih, b_hh, s_part);
            __syncthreads();
            if (t == 0 && k + DEPTH < n) {
                const float* src = tileA(tb + k + DEPTH, attn_W, W_hh, RL, row0, mat, vecoff);
                tma_issue(slot_addr[s], src, SLOT_FLOATS * 4, bar_addr[s]);
            }
        }
    }
    grid_barrier(1);

    // ===== Phase B: softmax (block-redundant) + TMA-pipelined enc sum =======
    {
        float sc[4];
        float m = -1e30f;
#pragma unroll
        for (int k = 0; k < 4; k++) {
            sc[k] = g_scores[t + k * 1024];
            m = fmaxf(m, sc[k]);
        }
        m = warp_max(m);
        if (lane == 0) red[warp] = m;
        __syncthreads();
        if (warp == 0) {
            float x = red[lane];
            x = warp_max(x);
            if (lane == 0) bcast = x;
        }
        __syncthreads();
        const float M = bcast;

        float sum = 0.0f;
#pragma unroll
        for (int k = 0; k < 4; k++) sum += expf(sc[k] - M);
        sum = warp_sum(sum);
        __syncthreads();
        if (lane == 0) red[warp] = sum;
        __syncthreads();
        if (warp == 0) {
            float x = red[lane];
            x = warp_sum(x);
            if (lane == 0) bcast = x;
        }
        __syncthreads();
        const float invS = 1.0f / bcast;

        const int rb0 = b * 28;
        const int nrows = (rb0 < L) ? ((L - rb0 < 28) ? (L - rb0) : 28) : 0;
        if (t < nrows) {
            float w = expf(g_scores[rb0 + t] - M) * invS;
            s_wts[t] = w;
            attn_out[rb0 + t] = w;
        }
        __syncthreads();

        const int nt = (nrows + 6) / 7;        // 7-row (28 KB) tiles
        if (t == 0) {
            for (int k = 0; k < (nt < DEPTH ? nt : DEPTH); k++) {
                int r0 = k * 7;
                int nr = (nrows - r0 < 7) ? (nrows - r0) : 7;
                tma_issue(slot_addr[k], enc + (size_t)(rb0 + r0) * H,
                          (unsigned)nr * H * 4, bar_addr[k]);
            }
        }
        float acc = 0.0f;
        for (int k = 0; k < nt; k++) {
            int s = k % DEPTH;
            mbar_wait(bar_addr[s], par[s]);
            par[s] ^= 1;
            int r0 = k * 7;
            int nr = (nrows - r0 < 7) ? (nrows - r0) : 7;
            const float* sl = ring + s * SLOT_FLOATS;
#pragma unroll
            for (int r = 0; r < 7; r++)
                if (r < nr) acc += s_wts[r0 + r] * sl[r * H + t];
            __syncthreads();
        }
        if (nrows > 0) atomicAdd(&g_attn[t], acc);
    }
    grid_barrier(0);

    // ===== Phase C: x = relu(comb_W @ [emb; attn] + b), TMA pipelined =======
    {
        s_vec[H + t] = g_attn[t];              // emb still in s_vec[0:H)
        __syncthreads();
        const int tb = (b * 256) / NB, te = ((b + 1) * 256) / NB;
        const int n = te - tb;
        if (t == 0) {
            for (int k = 0; k < (n < DEPTH ? n : DEPTH); k++)
                tma_issue(slot_addr[k], comb_W + (size_t)(tb + k) * SLOT_FLOATS,
                          SLOT_FLOATS * 4, bar_addr[k]);
        }
        for (int k = 0; k < n; k++) {
            int s = k % DEPTH;
            mbar_wait(bar_addr[s], par[s]);
            par[s] ^= 1;
            consume_dot((const float4*)(ring + s * SLOT_FLOATS),
                        (const float4*)s_vec, 2048, (tb + k) * 4, 2,
                        attn_b, comb_b, b_ih, b_hh, s_part);
            __syncthreads();
            if (t == 0 && k + DEPTH < n)
                tma_issue(slot_addr[s], comb_W + (size_t)(tb + k + DEPTH) * SLOT_FLOATS,
                          SLOT_FLOATS * 4, bar_addr[s]);
        }
    }
    grid_barrier(1);

    // ===== Phase D: gates = W_ih @ x + hh + biases, TMA pipelined ===========
    {
        s_vec[t] = g_x[t];
        __syncthreads();
        const int tb = (b * 512) / NB, te = ((b + 1) * 512) / NB;
        const int n = te - tb;
        if (t == 0) {
            for (int k = 0; k < (n < DEPTH ? n : DEPTH); k++)
                tma_issue(slot_addr[k], W_ih + (size_t)(tb + k) * SLOT_FLOATS,
                          SLOT_FLOATS * 4, bar_addr[k]);
        }
        for (int k = 0; k < n; k++) {
            int s = k % DEPTH;
            mbar_wait(bar_addr[s], par[s]);
            par[s] ^= 1;
            consume_dot((const float4*)(ring + s * SLOT_FLOATS),
                        (const float4*)s_vec, 1024, (tb + k) * 8, 3,
                        attn_b, comb_b, b_ih, b_hh, s_part);
            __syncthreads();
            if (t == 0 && k + DEPTH < n)
                tma_issue(slot_addr[s], W_ih + (size_t)(tb + k + DEPTH) * SLOT_FLOATS,
                          SLOT_FLOATS * 4, bar_addr[s]);
        }
    }
    grid_barrier(0);

    // ===== Phase E: LSTM pointwise + out proj + log_softmax (block 0) =======
    if (b == 0) {
        float ig = g_gates[t];
        float fg = g_gates[H + t];
        float gg = g_gates[2 * H + t];
        float og = g_gates[3 * H + t];
        float c = sigmoidf_(fg) * c0[t] + sigmoidf_(ig) * tanhf(gg);
        float h = sigmoidf_(og) * tanhf(c);
        out[V + t] = h;
        out[V + H + t] = c;
        s_vec[t] = h;
        __syncthreads();

        const float4* hv = (const float4*)s_vec;
        if (warp < V) {
            const float4* wr = (const float4*)(out_W + (size_t)warp * H);
            float acc = 0.0f;
#pragma unroll
            for (int k = lane; k < H / 4; k += 32) acc += dot4(wr[k], hv[k]);
            acc = warp_sum(acc);
            if (lane == 0) z[warp] = acc + out_b[warp];
        }
        __syncthreads();

        if (t == 0) {
            float m = -1e30f;
            for (int r = 0; r < V; r++) m = fmaxf(m, z[r]);
            float ssum = 0.0f;
            for (int r = 0; r < V; r++) ssum += expf(z[r] - m);
            float ls = m + logf(ssum);
            for (int r = 0; r < V; r++) out[r] = z[r] - ls;
        }
    }
}

// ---------------- launch ------------------------------------------------------
extern "C" void kernel_launch(void* const* d_in, const int* in_sizes, int n_in,
                              void* d_out, int out_size) {
    const int*   tok    = (const int*)  d_in[0];
    const float* h0     = (const float*)d_in[1];
    const float* c0     = (const float*)d_in[2];
    const float* enc    = (const float*)d_in[3];
    const float* emb    = (const float*)d_in[4];
    const float* attn_W = (const float*)d_in[5];
    const float* attn_b = (const float*)d_in[6];
    const float* comb_W = (const float*)d_in[7];
    const float* comb_b = (const float*)d_in[8];
    const float* W_ih   = (const float*)d_in[9];
    const float* W_hh   = (const float*)d_in[10];
    const float* b_ih   = (const float*)d_in[11];
    const float* b_hh   = (const float*)d_in[12];
    const float* out_W  = (const float*)d_in[13];
    const float* out_b  = (const float*)d_in[14];
    float* out = (float*)d_out;

    cudaFuncSetAttribute(k_decoder, cudaFuncAttributeMaxDynamicSharedMemorySize,
                         SMEM_BYTES);
    k_decoder<<<NB, NT, SMEM_BYTES>>>(tok, h0, c0, enc, emb, attn_W, attn_b,
                                      comb_W, comb_b, W_ih, W_hh, b_ih, b_hh,
                                      out_W, out_b, out);
}

// round 10
// speedup vs baseline: 1.5484x; 1.5484x over previous
#include <cuda_runtime.h>
#include <math.h>

#define H 1024
#define L 4096
#define V 29
#define NB 148
#define NT 1024
#define WPB 32
#define WTOT (NB * WPB)   // 4736 warps

// ---------------- scratch (device globals) ----------------------------------
__device__ float g_scp4[4 * L];        // score quarter-partials [4*row+q]
__device__ float g_hhp[8 * H];         // W_hh half-partials [2*row+h]
__device__ float g_attn[H];
__device__ float g_xp[4 * H];          // comb quarter-partials
__device__ float g_gp[8 * H];          // W_ih half-partials
__device__ unsigned g_cnt = 0;
__device__ volatile unsigned g_flag = 0;

// ---------------- helpers ----------------------------------------------------
__device__ __forceinline__ float warp_sum(float v) {
#pragma unroll
    for (int o = 16; o; o >>= 1) v += __shfl_xor_sync(0xffffffffu, v, o);
    return v;
}
__device__ __forceinline__ float warp_max(float v) {
#pragma unroll
    for (int o = 16; o; o >>= 1) v = fmaxf(v, __shfl_xor_sync(0xffffffffu, v, o));
    return v;
}
__device__ __forceinline__ float sigmoidf_(float x) { return 1.0f / (1.0f + expf(-x)); }
__device__ __forceinline__ float dot4(float4 a, float4 b) {
    return a.x * b.x + a.y * b.y + a.z * b.z + a.w * b.w;
}

__device__ __forceinline__ void grid_barrier(unsigned sense) {
    __syncthreads();
    if (threadIdx.x == 0) {
        __threadfence();
        unsigned old = atomicAdd(&g_cnt, 1u);
        if (old == NB - 1) {
            g_cnt = 0;
            __threadfence();
            g_flag = sense;
        } else {
            while (g_flag != sense) { __nanosleep(32); }
        }
        __threadfence();
    }
    __syncthreads();
}

// ---------------- software-pipelined unit stream ------------------------------
// A unit = 512 consecutive floats (4 float4 per lane). This warp processes
// units [u0,u1) of the region at Wbase, dotting each against the smem vector
// slot (u & vmask)*512, storing the warp-reduced partial to dst[u].
// Double-buffered: unit u+1's global loads are issued BEFORE unit u's reduce.
__device__ __forceinline__ void stream_units(const float* __restrict__ Wbase,
                                             int u0, int u1,
                                             const float4* __restrict__ v,
                                             int vmask,
                                             float* __restrict__ dst,
                                             int lane) {
    if (u0 >= u1) return;
    const float4* gp = (const float4*)Wbase;
    float4 b0[4], b1[4];
#pragma unroll
    for (int k = 0; k < 4; k++) b0[k] = gp[(size_t)u0 * 128 + lane + 32 * k];
    for (int u = u0; u < u1; u++) {
        bool even = ((u - u0) & 1) == 0;
        if (u + 1 < u1) {
            const float4* np = gp + (size_t)(u + 1) * 128 + lane;
            if (even) {
#pragma unroll
                for (int k = 0; k < 4; k++) b1[k] = np[32 * k];
            } else {
#pragma unroll
                for (int k = 0; k < 4; k++) b0[k] = np[32 * k];
            }
        }
        const float4* vp = v + (u & vmask) * 128 + lane;
        float p;
        if (even)
            p = dot4(b0[0], vp[0])  + dot4(b0[1], vp[32]) +
                dot4(b0[2], vp[64]) + dot4(b0[3], vp[96]);
        else
            p = dot4(b1[0], vp[0])  + dot4(b1[1], vp[32]) +
                dot4(b1[2], vp[64]) + dot4(b1[3], vp[96]);
        p = warp_sum(p);
        if (lane == 0) dst[u] = p;
    }
}

#define WRANGE(NU, u0, u1)                                          \
    int u0 = (int)(((long long)wg * (NU)) / WTOT);                  \
    int u1 = (int)(((long long)(wg + 1) * (NU)) / WTOT);

// ---------------- the whole decoder step in one kernel -----------------------
__global__ void __launch_bounds__(NT, 1)
k_decoder(const int* __restrict__ tok,
          const float* __restrict__ h0,
          const float* __restrict__ c0,
          const float* __restrict__ enc,
          const float* __restrict__ emb,
          const float* __restrict__ attn_W,
          const float* __restrict__ attn_b,
          const float* __restrict__ comb_W,
          const float* __restrict__ comb_b,
          const float* __restrict__ W_ih,
          const float* __restrict__ W_hh,
          const float* __restrict__ b_ih,
          const float* __restrict__ b_hh,
          const float* __restrict__ out_W,
          const float* __restrict__ out_b,
          float* __restrict__ out) {
    __shared__ float s_vec[2 * H];
    __shared__ float red[32];
    __shared__ float bcast;
    __shared__ float wts[28];
    __shared__ float z[32];

    const int t = threadIdx.x;
    const int warp = t >> 5, lane = t & 31;
    const int b = blockIdx.x;
    const int wg = b * WPB + warp;
    float* attn_out = out + V + 2 * H;          // [lp | h | c | attn_w]

    // ===== Phase A: attn scores (quarters) + W_hh@h0 (halves) ===============
    {
        const float* erow = emb + (size_t)tok[0] * H;
        s_vec[t] = erow[t];
        s_vec[H + t] = h0[t];
        if (b == 0) g_attn[t] = 0.0f;
        __syncthreads();

        {   // attn_W: 16384 units (4 per row of 2048)
            WRANGE(16384, u0, u1);
            stream_units(attn_W, u0, u1, (const float4*)s_vec, 3, g_scp4, lane);
        }
        {   // W_hh: 8192 units (2 per row of 1024), v = h0
            WRANGE(8192, u0, u1);
            stream_units(W_hh, u0, u1, (const float4*)(s_vec + H), 1, g_hhp, lane);
        }
    }
    grid_barrier(1);

    // ===== Phase B: softmax (block-redundant) + weighted encoder sum ========
    {
        const float4* sq = (const float4*)g_scp4;
        float sc[4];
        float m = -1e30f;
#pragma unroll
        for (int k = 0; k < 4; k++) {
            float4 q = sq[t + k * 1024];
            sc[k] = q.x + q.y + q.z + q.w + attn_b[t + k * 1024];
            m = fmaxf(m, sc[k]);
        }
        m = warp_max(m);
        if (lane == 0) red[warp] = m;
        __syncthreads();
        if (warp == 0) {
            float x = red[lane];
            x = warp_max(x);
            if (lane == 0) bcast = x;
        }
        __syncthreads();
        const float M = bcast;

        float sum = 0.0f;
#pragma unroll
        for (int k = 0; k < 4; k++) sum += expf(sc[k] - M);
        sum = warp_sum(sum);
        __syncthreads();
        if (lane == 0) red[warp] = sum;
        __syncthreads();
        if (warp == 0) {
            float x = red[lane];
            x = warp_sum(x);
            if (lane == 0) bcast = x;
        }
        __syncthreads();
        const float invS = 1.0f / bcast;

        const int lb = b * 28;
        const int nr = (lb < L) ? ((L - lb < 28) ? (L - lb) : 28) : 0;
        if (t < nr) {
            float4 q = sq[lb + t];
            float w = expf(q.x + q.y + q.z + q.w + attn_b[lb + t] - M) * invS;
            wts[t] = w;
            attn_out[lb + t] = w;
        }
        __syncthreads();

        if (nr > 0) {
            float acc = 0.0f;
            const float* e = enc + (size_t)lb * H + t;
#pragma unroll 7
            for (int r = 0; r < nr; r++) acc += wts[r] * e[(size_t)r * H];
            atomicAdd(&g_attn[t], acc);
        }
    }
    grid_barrier(0);

    // ===== Phase C: comb quarters = comb_W @ [emb; attn] ====================
    {
        s_vec[H + t] = g_attn[t];        // emb still in s_vec[0:H)
        __syncthreads();
        WRANGE(4096, u0, u1);            // 4 units per row of 2048
        stream_units(comb_W, u0, u1, (const float4*)s_vec, 3, g_xp, lane);
    }
    grid_barrier(1);

    // ===== Phase D: x build + W_ih halves ===================================
    {
        const float4* xp4 = (const float4*)g_xp;
        float4 p = xp4[t];
        s_vec[t] = fmaxf(p.x + p.y + p.z + p.w + comb_b[t], 0.0f);
        __syncthreads();
        WRANGE(8192, u0, u1);            // 2 units per row of 1024
        stream_units(W_ih, u0, u1, (const float4*)s_vec, 1, g_gp, lane);
    }
    grid_barrier(0);

    // ===== Phase E: LSTM pointwise + out proj + log_softmax (block 0) =======
    if (b == 0) {
        const float2* gp = (const float2*)g_gp;
        const float2* hp = (const float2*)g_hhp;
        float2 pi = gp[t],         hi = hp[t];
        float2 pf = gp[H + t],     hf = hp[H + t];
        float2 pg = gp[2 * H + t], hg = hp[2 * H + t];
        float2 po = gp[3 * H + t], ho = hp[3 * H + t];
        float ig = pi.x + pi.y + hi.x + hi.y + b_ih[t]         + b_hh[t];
        float fg = pf.x + pf.y + hf.x + hf.y + b_ih[H + t]     + b_hh[H + t];
        float gg = pg.x + pg.y + hg.x + hg.y + b_ih[2 * H + t] + b_hh[2 * H + t];
        float og = po.x + po.y + ho.x + ho.y + b_ih[3 * H + t] + b_hh[3 * H + t];
        float c = sigmoidf_(fg) * c0[t] + sigmoidf_(ig) * tanhf(gg);
        float h = sigmoidf_(og) * tanhf(c);
        out[V + t] = h;
        out[V + H + t] = c;
        s_vec[t] = h;
        __syncthreads();

        const float4* hv = (const float4*)s_vec;
        if (warp < V) {
            const float4* wr = (const float4*)(out_W + (size_t)warp * H);
            float acc = 0.0f;
#pragma unroll
            for (int k = lane; k < H / 4; k += 32) acc += dot4(wr[k], hv[k]);
            acc = warp_sum(acc);
            if (lane == 0) z[warp] = acc + out_b[warp];
        }
        __syncthreads();

        if (t == 0) {
            float m = -1e30f;
            for (int r = 0; r < V; r++) m = fmaxf(m, z[r]);
            float ssum = 0.0f;
            for (int r = 0; r < V; r++) ssum += expf(z[r] - m);
            float ls = m + logf(ssum);
            for (int r = 0; r < V; r++) out[r] = z[r] - ls;
        }
    }
}

// ---------------- launch ------------------------------------------------------
extern "C" void kernel_launch(void* const* d_in, const int* in_sizes, int n_in,
                              void* d_out, int out_size) {
    const int*   tok    = (const int*)  d_in[0];
    const float* h0     = (const float*)d_in[1];
    const float* c0     = (const float*)d_in[2];
    const float* enc    = (const float*)d_in[3];
    const float* emb    = (const float*)d_in[4];
    const float* attn_W = (const float*)d_in[5];
    const float* attn_b = (const float*)d_in[6];
    const float* comb_W = (const float*)d_in[7];
    const float* comb_b = (const float*)d_in[8];
    const float* W_ih   = (const float*)d_in[9];
    const float* W_hh   = (const float*)d_in[10];
    const float* b_ih   = (const float*)d_in[11];
    const float* b_hh   = (const float*)d_in[12];
    const float* out_W  = (const float*)d_in[13];
    const float* out_b  = (const float*)d_in[14];
    float* out = (float*)d_out;

    k_decoder<<<NB, NT>>>(tok, h0, c0, enc, emb, attn_W, attn_b,
                          comb_W, comb_b, W_ih, W_hh, b_ih, b_hh,
                          out_W, out_b, out);
}